// round 2
// baseline (speedup 1.0000x reference)
#include <cuda_runtime.h>
#include <cuda_fp16.h>
#include <cstdint>

// ============================================================
// QuaternionLinear as one 4096x4096x4096 fp16 GEMM (mma.sync)
//   out = x_flat(4096x4096) @ W'^T(4096x4096) + bias
// tcgen05 is unavailable: harness compiles via compute_103 PTX
// which rejects sm_103a-specific instructions. Classic HMMA path.
// ============================================================

#define BATCH   4096
#define KDIM    4096
#define NDIM    4096

#define BM      128
#define BN      128
#define BK      64          // halves per K-tile (128 bytes per row)
#define NK      (KDIM / BK) // 64
#define STAGES  3

#define A_TILE_BYTES (BM * 128)   // 16384
#define B_TILE_BYTES (BN * 128)   // 16384
#define STAGE_BYTES  (A_TILE_BYTES + B_TILE_BYTES)   // 32768
#define SMEM_TOTAL   (STAGES * STAGE_BYTES)          // 98304

// fp16 scratch (device globals: allocation-free per harness rules)
__device__ __align__(128) __half g_Ah[(size_t)BATCH * KDIM];
__device__ __align__(128) __half g_Bh[(size_t)NDIM * KDIM];

// ---------------- helpers ----------------
__device__ __forceinline__ uint32_t smem_u32(const void* p) {
    uint32_t a;
    asm("{ .reg .u64 t; cvta.to.shared.u64 t, %1; cvt.u32.u64 %0, t; }" : "=r"(a) : "l"(p));
    return a;
}
__device__ __forceinline__ void cp_async16(uint32_t dst, const void* src) {
    asm volatile("cp.async.cg.shared.global [%0], [%1], 16;\n" :: "r"(dst), "l"(src));
}
#define CP_COMMIT() asm volatile("cp.async.commit_group;\n" ::: "memory")
#define CP_WAIT(n)  asm volatile("cp.async.wait_group %0;\n" :: "n"(n) : "memory")

__device__ __forceinline__ void ldm_x4(uint32_t* r, uint32_t addr) {
    asm volatile("ldmatrix.sync.aligned.m8n8.x4.shared.b16 {%0,%1,%2,%3}, [%4];"
        : "=r"(r[0]), "=r"(r[1]), "=r"(r[2]), "=r"(r[3]) : "r"(addr));
}
__device__ __forceinline__ void mma16816(float* c, const uint32_t* a, const uint32_t* b) {
    asm volatile(
        "mma.sync.aligned.m16n8k16.row.col.f32.f16.f16.f32 "
        "{%0,%1,%2,%3}, {%4,%5,%6,%7}, {%8,%9}, {%0,%1,%2,%3};"
        : "+f"(c[0]), "+f"(c[1]), "+f"(c[2]), "+f"(c[3])
        : "r"(a[0]), "r"(a[1]), "r"(a[2]), "r"(a[3]), "r"(b[0]), "r"(b[1]));
}
__device__ __forceinline__ uint32_t sw128(uint32_t off) {
    return off ^ ((off >> 3) & 0x70);
}

// ---------------- Prep kernels ----------------
__global__ void convert_x_kernel(const float4* __restrict__ x) {
    int i = blockIdx.x * blockDim.x + threadIdx.x;
    if (i >= (BATCH * KDIM) / 4) return;
    float4 v = x[i];
    __half2* dst = reinterpret_cast<__half2*>(g_Ah);
    dst[2 * i]     = __floats2half2_rn(v.x, v.y);
    dst[2 * i + 1] = __floats2half2_rn(v.z, v.w);
}

__global__ void build_w_kernel(const float4* __restrict__ w) {
    int gid = blockIdx.x * blockDim.x + threadIdx.x;  // (oc, i)
    if (gid >= NDIM * 1024) return;
    int i  = gid & 1023;
    int oc = gid >> 10;
    int c  = oc & 3;
    int o  = oc >> 2;
    float4 v = w[o * 1024 + i];
    float wv[4] = {v.x, v.y, v.z, v.w};
    // out_c coefficient of a_d is sign[c][d] * w[comp[c][d]]
    const int  comp[4][4] = {{0,1,2,3},{1,0,3,2},{2,3,0,1},{3,2,1,0}};
    const float sgn[4][4] = {{1.f,-1.f,-1.f,-1.f},{1.f,1.f,1.f,-1.f},
                             {1.f,-1.f,1.f,1.f},{1.f,1.f,-1.f,1.f}};
    __half2* dst = reinterpret_cast<__half2*>(g_Bh);
    dst[2 * gid]     = __floats2half2_rn(sgn[c][0]*wv[comp[c][0]], sgn[c][1]*wv[comp[c][1]]);
    dst[2 * gid + 1] = __floats2half2_rn(sgn[c][2]*wv[comp[c][2]], sgn[c][3]*wv[comp[c][3]]);
}

// ---------------- GEMM ----------------
__device__ __forceinline__ void load_stage(uint32_t sbase, int slot, int kt,
                                           int m0, int n0, int tid) {
    uint32_t st = sbase + slot * STAGE_BYTES;
    int k0 = kt * BK;
    const __half* Ap = g_Ah + ((size_t)m0 << 12) + k0;
    const __half* Bp = g_Bh + ((size_t)n0 << 12) + k0;
#pragma unroll
    for (int c = 0; c < BM * 8; c += 256) {          // A: 1024 16B chunks
        int cc = c + tid;
        int row = cc >> 3, col = cc & 7;
        uint32_t sw = sw128((uint32_t)((row << 7) | (col << 4)));
        cp_async16(st + sw, Ap + ((size_t)row << 12) + (col << 3));
    }
#pragma unroll
    for (int c = 0; c < BN * 8; c += 256) {          // B: 1024 16B chunks
        int cc = c + tid;
        int row = cc >> 3, col = cc & 7;
        uint32_t sw = sw128((uint32_t)((row << 7) | (col << 4)));
        cp_async16(st + A_TILE_BYTES + sw, Bp + ((size_t)row << 12) + (col << 3));
    }
}

__global__ void __launch_bounds__(256, 2) qgemm_kernel(const float* __restrict__ bias,
                                                       float* __restrict__ out) {
    extern __shared__ char smem[];
    uint32_t sbase = smem_u32(smem);
    int tid = threadIdx.x;
    int wid = tid >> 5;
    int lid = tid & 31;
    int m0 = blockIdx.y * BM;
    int n0 = blockIdx.x * BN;

    int warp_m = wid & 1;   // 2 warps along M (64 rows each)
    int warp_n = wid >> 1;  // 4 warps along N (32 cols each)

    float acc[4][4][4];     // [m-tile16][n-tile8][4]
#pragma unroll
    for (int i = 0; i < 4; ++i)
#pragma unroll
        for (int j = 0; j < 4; ++j)
#pragma unroll
            for (int v = 0; v < 4; ++v) acc[i][j][v] = 0.f;

    // Prologue: stages 0 .. STAGES-2
#pragma unroll
    for (int s = 0; s < STAGES - 1; ++s) {
        load_stage(sbase, s, s, m0, n0, tid);
        CP_COMMIT();
    }

    // Precompute per-lane ldmatrix row/col components
    int a_mat = lid >> 3;            // 0..3
    int a_r   = lid & 7;
    int a_row_base = warp_m * 64 + (a_mat & 1) * 8 + a_r;   // + mt*16
    int a_kb_base  = (a_mat >> 1) * 16;                     // + k0*2
    int b_row_base = warp_n * 32 + (a_mat >> 1) * 8 + a_r;  // + ntp*16
    int b_kb_base  = (a_mat & 1) * 16;                      // + k0*2

    for (int k = 0; k < NK; ++k) {
        int kload = k + STAGES - 1;
        if (kload < NK) load_stage(sbase, kload % STAGES, kload, m0, n0, tid);
        CP_COMMIT();
        CP_WAIT(STAGES - 2);
        __syncthreads();

        uint32_t a_base = sbase + (k % STAGES) * STAGE_BYTES;
        uint32_t b_base = a_base + A_TILE_BYTES;

#pragma unroll
        for (int ks = 0; ks < BK / 16; ++ks) {
            int kb = ks * 32;   // byte offset of k0 within row
            uint32_t af[4][4];
#pragma unroll
            for (int mt = 0; mt < 4; ++mt) {
                uint32_t off = (uint32_t)((a_row_base + mt * 16) << 7) + kb + a_kb_base;
                ldm_x4(af[mt], a_base + sw128(off));
            }
            uint32_t bf[8];
#pragma unroll
            for (int ntp = 0; ntp < 2; ++ntp) {
                uint32_t off = (uint32_t)((b_row_base + ntp * 16) << 7) + kb + b_kb_base;
                ldm_x4(&bf[ntp * 4], b_base + sw128(off));
            }
#pragma unroll
            for (int mt = 0; mt < 4; ++mt)
#pragma unroll
                for (int nt = 0; nt < 4; ++nt)
                    mma16816(acc[mt][nt], af[mt], &bf[nt * 2]);
        }
        __syncthreads();
    }

    // Epilogue: direct coalesced-ish float2 stores + bias
    int qrow = lid >> 2;        // 0..7
    int qcol = (lid & 3) * 2;   // 0,2,4,6
#pragma unroll
    for (int nt = 0; nt < 4; ++nt) {
        int gn = n0 + warp_n * 32 + nt * 8 + qcol;
        float b0 = __ldg(bias + gn);
        float b1 = __ldg(bias + gn + 1);
#pragma unroll
        for (int mt = 0; mt < 4; ++mt) {
            int gm = m0 + warp_m * 64 + mt * 16 + qrow;
            float2 v0 = {acc[mt][nt][0] + b0, acc[mt][nt][1] + b1};
            float2 v1 = {acc[mt][nt][2] + b0, acc[mt][nt][3] + b1};
            *reinterpret_cast<float2*>(out + (size_t)gm * NDIM + gn) = v0;
            *reinterpret_cast<float2*>(out + (size_t)(gm + 8) * NDIM + gn) = v1;
        }
    }
}

// ---------------- launch ----------------
extern "C" void kernel_launch(void* const* d_in, const int* in_sizes, int n_in,
                              void* d_out, int out_size) {
    const float* x    = (const float*)d_in[0];
    const float* w    = (const float*)d_in[1];
    const float* bias = (const float*)d_in[2];
    float* out = (float*)d_out;

    convert_x_kernel<<<(BATCH * KDIM / 4 + 255) / 256, 256>>>((const float4*)x);
    build_w_kernel<<<(NDIM * 1024 + 255) / 256, 256>>>((const float4*)w);

    cudaFuncSetAttribute(qgemm_kernel, cudaFuncAttributeMaxDynamicSharedMemorySize, SMEM_TOTAL);
    dim3 grid(NDIM / BN, BATCH / BM);   // (32, 32)
    qgemm_kernel<<<grid, 256, SMEM_TOTAL>>>(bias, out);
}